// round 3
// baseline (speedup 1.0000x reference)
#include <cuda_runtime.h>
#include <cuda_bf16.h>
#include <cstdint>

typedef unsigned long long ull;

#define NB 128      // batches
#define NN 1024     // vector length
#define NT 16       // 1024/64 tiles per dim
#define WS 68       // Wt row stride (floats)
#define VS2 260     // Vt2 row stride (floats), rows are 256 duplicated floats
#define XS 132      // Xi row stride (floats)

// Shared layout (floats)
#define OFF_WT 0                     // Wt[j 0..31][i 0..63]        : 32*68  = 2176
#define OFF_V2 2176                  // Vt2[j 0..31][2x dup 0..255] : 32*260 = 8320
#define OFF_XI (2176 + 8320)         // Xi[i 0..63][x 0..127]       : 64*132 = 8448
#define OFF_RT (OFF_XI + 8448)       // rt[64]
#define OFF_CT (OFF_RT + 64)         // ct[32]
#define OFF_S  (OFF_CT + 32)         // ssh[128]
#define SMEM_FLOATS (OFF_S + 128)
#define SMEM_BYTES  (SMEM_FLOATS * 4)

// Packed f32x2 FMA (Blackwell)
#define FMA2(d, a, b, c) \
    asm("fma.rn.f32x2 %0, %1, %2, %3;" : "=l"(d) : "l"(a), "l"(b), "l"(c))

__device__ __forceinline__ void unpack2(ull s, float& lo, float& hi) {
    unsigned int a, b;
    asm("mov.b64 {%0, %1}, %2;" : "=r"(a), "=r"(b) : "l"(s));
    lo = __uint_as_float(a);
    hi = __uint_as_float(b);
}

// energy_b = S0 - v_b.(r+c) + 2 * v_b^T U v_b,  U = triu(W)
// One block per (upper-tri 64x64 tile, 32-wide j-half). 272 blocks.
__global__ void __launch_bounds__(256, 2)
potts_quad_kernel(const float* __restrict__ V, const float* __restrict__ W,
                  float* __restrict__ out)
{
    // decode (ti, tj, kh)
    int bid = blockIdx.x;
    int kh  = bid & 1;
    int h   = bid >> 1;            // 0..135
    int ti  = 0;
    while (h >= NT - ti) { h -= NT - ti; ++ti; }
    int tj  = ti + h;

    extern __shared__ float sh[];
    float* Wt  = sh + OFF_WT;
    float* V2  = sh + OFF_V2;
    float* Xi  = sh + OFF_XI;
    float* rt  = sh + OFF_RT;
    float* ct  = sh + OFF_CT;
    float* ssh = sh + OFF_S;

    const int tid = threadIdx.x;
    const int I0 = ti * 64;
    const int J0 = tj * 64 + kh * 32;

    // ---- Fill Wt[j][i] = triu-mask(W[I0+i][J0+j]) ----
    // lanes traverse i -> conflict-free STS; LDG.128 row gathers (L2 hits)
    {
        int i   = tid & 63;
        int jq0 = tid >> 6;                 // 0..3
        int gi  = I0 + i;
        const float* Wrow = W + (size_t)gi * NN + J0;
        #pragma unroll
        for (int q = 0; q < 2; ++q) {
            int jq = jq0 + q * 4;           // 0..7
            int j  = jq * 4;
            float4 w4 = *reinterpret_cast<const float4*>(Wrow + j);
            int gj = J0 + j;
            Wt[(j + 0) * WS + i] = (gi <= gj + 0) ? w4.x : 0.0f;
            Wt[(j + 1) * WS + i] = (gi <= gj + 1) ? w4.y : 0.0f;
            Wt[(j + 2) * WS + i] = (gi <= gj + 2) ? w4.z : 0.0f;
            Wt[(j + 3) * WS + i] = (gi <= gj + 3) ? w4.w : 0.0f;
        }
    }
    // ---- Fill Vt2[j][2x]=(v,v) and Xi[i][x] ----
    // lanes traverse x -> conflict-free STS
    {
        int x    = tid & 127;
        int half = tid >> 7;                // 0/1
        const float* Vx = V + (size_t)x * NN;
        #pragma unroll
        for (int q = 0; q < 4; ++q) {
            int jq = half + 2 * q;          // 0..7
            int j  = jq * 4;
            float4 v4 = *reinterpret_cast<const float4*>(Vx + J0 + j);
            *reinterpret_cast<float2*>(&V2[(j + 0) * VS2 + 2 * x]) = make_float2(v4.x, v4.x);
            *reinterpret_cast<float2*>(&V2[(j + 1) * VS2 + 2 * x]) = make_float2(v4.y, v4.y);
            *reinterpret_cast<float2*>(&V2[(j + 2) * VS2 + 2 * x]) = make_float2(v4.z, v4.z);
            *reinterpret_cast<float2*>(&V2[(j + 3) * VS2 + 2 * x]) = make_float2(v4.w, v4.w);
        }
        #pragma unroll
        for (int q = 0; q < 8; ++q) {
            int iq = half + 2 * q;          // 0..15
            int i2 = iq * 4;
            float4 v4 = *reinterpret_cast<const float4*>(Vx + I0 + i2);
            Xi[(i2 + 0) * XS + x] = v4.x;
            Xi[(i2 + 1) * XS + x] = v4.y;
            Xi[(i2 + 2) * XS + x] = v4.z;
            Xi[(i2 + 3) * XS + x] = v4.w;
        }
    }
    __syncthreads();

    // ---- Register GEMM: 8 i (4 pairs) x 4 x per thread, k over 32 ----
    // per k: 4 x LDS.128 + 16 FMA2, zero MOVs
    const int ig = tid & 7;                 // i-group
    const int xg = tid >> 3;                // x-group 0..31
    const int i0 = ig * 8;
    const int x0 = xg * 4;

    const float* WtP = Wt + i0;
    const float* VtP = V2 + 8 * xg;

    ull acc[4][4];
    #pragma unroll
    for (int p = 0; p < 4; ++p)
        #pragma unroll
        for (int xx = 0; xx < 4; ++xx) acc[p][xx] = 0ull;

    #pragma unroll 8
    for (int k = 0; k < 32; ++k) {
        ulonglong2 wA = *reinterpret_cast<const ulonglong2*>(WtP + (size_t)k * WS);
        ulonglong2 wB = *reinterpret_cast<const ulonglong2*>(WtP + (size_t)k * WS + 4);
        ulonglong2 vA = *reinterpret_cast<const ulonglong2*>(VtP + (size_t)k * VS2);
        ulonglong2 vB = *reinterpret_cast<const ulonglong2*>(VtP + (size_t)k * VS2 + 4);
        const ull w_[4] = {wA.x, wA.y, wB.x, wB.y};   // (w_i, w_i+1) pairs
        const ull v_[4] = {vA.x, vA.y, vB.x, vB.y};   // (v_x, v_x) dups
        #pragma unroll
        for (int p = 0; p < 4; ++p)
            #pragma unroll
            for (int xx = 0; xx < 4; ++xx)
                FMA2(acc[p][xx], w_[p], v_[xx], acc[p][xx]);
    }

    // ---- Row/col sums of W half-tile (linear + constant terms) ----
    if (tid < 64) {
        float s = 0.0f;
        #pragma unroll 8
        for (int j = 0; j < 32; ++j) s += Wt[j * WS + tid];
        rt[tid] = s;
    } else if (tid < 96) {
        int j = tid - 64;
        float s = 0.0f;
        #pragma unroll 8
        for (int i = 0; i < 64; ++i) s += Wt[j * WS + i];
        ct[j] = s;
    }

    // ---- Quad epilogue: s[x] = sum_i Xi[i][x]*C[i][x]; reduce over ig via shuffle ----
    float s[4] = {0.0f, 0.0f, 0.0f, 0.0f};
    #pragma unroll
    for (int p = 0; p < 4; ++p) {
        float4 xlo = *reinterpret_cast<const float4*>(&Xi[(i0 + 2 * p) * XS + x0]);
        float4 xhi = *reinterpret_cast<const float4*>(&Xi[(i0 + 2 * p + 1) * XS + x0]);
        const float xl[4] = {xlo.x, xlo.y, xlo.z, xlo.w};
        const float xh[4] = {xhi.x, xhi.y, xhi.z, xhi.w};
        #pragma unroll
        for (int xx = 0; xx < 4; ++xx) {
            float alo, ahi;
            unpack2(acc[p][xx], alo, ahi);
            s[xx] += xl[xx] * alo + xh[xx] * ahi;
        }
    }
    #pragma unroll
    for (int off = 4; off >= 1; off >>= 1) {
        #pragma unroll
        for (int xx = 0; xx < 4; ++xx)
            s[xx] += __shfl_xor_sync(0xffffffffu, s[xx], off, 8);
    }
    if (ig == 0) {   // unique writer per x
        ssh[x0 + 0] = 2.0f * s[0];
        ssh[x0 + 1] = 2.0f * s[1];
        ssh[x0 + 2] = 2.0f * s[2];
        ssh[x0 + 3] = 2.0f * s[3];
    }
    __syncthreads();

    // ---- Linear + constant + single global atomic ----
    if (tid < NB) {
        float e = ssh[tid];
        #pragma unroll 8
        for (int i = 0; i < 64; ++i) e += rt[i] * (1.0f - Xi[i * XS + tid]);
        #pragma unroll 8
        for (int j = 0; j < 32; ++j) e -= ct[j] * V2[j * VS2 + 2 * tid];
        atomicAdd(&out[tid], e);
    }
}

extern "C" void kernel_launch(void* const* d_in, const int* in_sizes, int n_in,
                              void* d_out, int out_size) {
    const float* V = (const float*)d_in[0];   // vector       [128,1024]
    const float* W = (const float*)d_in[1];   // interactions [1024,1024]
    if (n_in >= 2 && in_sizes[0] > in_sizes[1]) {
        V = (const float*)d_in[1];
        W = (const float*)d_in[0];
    }
    float* out = (float*)d_out;

    cudaMemsetAsync(out, 0, (size_t)out_size * sizeof(float));

    cudaFuncSetAttribute(potts_quad_kernel,
                         cudaFuncAttributeMaxDynamicSharedMemorySize, SMEM_BYTES);
    const int nblocks = (NT * (NT + 1) / 2) * 2;   // 136 upper tiles x 2 halves = 272
    potts_quad_kernel<<<nblocks, 256, SMEM_BYTES>>>(V, W, out);
}